// round 16
// baseline (speedup 1.0000x reference)
#include <cuda_runtime.h>
#include <cuda_bf16.h>
#include <cstdint>
#include <stdint.h>
#include <math.h>

#define BB   8
#define SS   1024
#define DDIM 768
#define HH   8
#define DKK  96
#define FFD  1024
#define BHN  (BB*HH)    // 64
#define MROWS (BB*SS)   // 8192
#define DP   (DDIM/2)   // 384 pairs
#define FP   (FFD/2)    // 512 pairs
#define SP   (SS/2)     // 512 w-pairs per row

// bf16-exact mask value: bf16(-1e9) = -998244352.0f (0xCE6E0000)
#define MASKV -998244352.0f

// ---------------- scratch (device globals: allocation-free rule) ------------
__device__ uint32_t g_wb[BHN*SS*SP];   // 128 MB bf16-pair score tensor (lower tri)
__device__ float g_cm[BHN*SS];
__device__ float g_ci[BHN*SS];
__device__ float g_kv[MROWS*DDIM];     // f32 kv (pack_v source)
__device__ float g_t0[MROWS*DDIM];
__device__ float g_x1[MROWS*DDIM];
__device__ float g_x2[MROWS*DDIM];
__device__ int   g_mask_u8;

// packed bf16 buffers
__device__ uint32_t g_xh [MROWS*DP];
__device__ uint32_t g_qh [MROWS*DP];
__device__ uint32_t g_kvh[MROWS*DP];
__device__ uint32_t g_x1h[MROWS*DP], g_x1l[MROWS*DP];
__device__ uint32_t g_x2h[MROWS*DP], g_x2l[MROWS*DP];
__device__ uint32_t g_hh [MROWS*FP], g_hl [MROWS*FP];
__device__ uint32_t g_vh [BHN*512*DKK];          // V pairs over seq, hi only
__device__ uint32_t g_w1qh[DP*DDIM], g_w1vh[DP*DDIM];
__device__ uint32_t g_w2qh[DP*DDIM], g_w2vh[DP*DDIM];
__device__ uint32_t g_wf1h[DP*FFD],  g_wf1l[DP*FFD];
__device__ uint32_t g_wf2h[FP*DDIM], g_wf2l[FP*DDIM];

// ---------------- cp.async helpers ------------------------------------------
__device__ __forceinline__ uint32_t smem_u32(const void* p) {
    return (uint32_t)__cvta_generic_to_shared(p);
}
#define CP16(dst, src) asm volatile("cp.async.cg.shared.global [%0], [%1], 16;\n" :: "r"(dst), "l"(src))
#define CPCOMMIT()     asm volatile("cp.async.commit_group;\n")
#define CPWAIT1()      asm volatile("cp.async.wait_group 1;\n")

// ---------------- mask dtype probe -----------------------------------------
__global__ void probe_mask_k(const unsigned char* __restrict__ p) {
    __shared__ int any;
    if (threadIdx.x == 0) any = 0;
    __syncthreads();
    int local = 0;
    for (int i = threadIdx.x; i < BB*SS; i += 256)
        if ((i & 3) && p[i]) local = 1;
    if (local) atomicOr(&any, 1);
    __syncthreads();
    if (threadIdx.x == 0) g_mask_u8 = any;
}

// ---------------- bf16 helpers ----------------------------------------------
__device__ __forceinline__ uint32_t pack2h(float x, float y) {
    __nv_bfloat162 t = __floats2bfloat162_rn(x, y);   // .x = low halfword
    return *(uint32_t*)&t;
}
__device__ __forceinline__ float2 unpack2(uint32_t u) {
    __nv_bfloat162 t = *(__nv_bfloat162*)&u;
    return make_float2(__bfloat162float(t.x), __bfloat162float(t.y));
}
__device__ __forceinline__ void split2(float x, float y, uint32_t& h, uint32_t& l) {
    __nv_bfloat16 xh = __float2bfloat16(x);
    __nv_bfloat16 yh = __float2bfloat16(y);
    __nv_bfloat16 xl = __float2bfloat16(x - __bfloat162float(xh));
    __nv_bfloat16 yl = __float2bfloat16(y - __bfloat162float(yh));
    h = ((uint32_t)__bfloat16_as_ushort(yh) << 16) | (uint32_t)__bfloat16_as_ushort(xh);
    l = ((uint32_t)__bfloat16_as_ushort(yl) << 16) | (uint32_t)__bfloat16_as_ushort(xl);
}

__device__ __forceinline__ void mma16816(float* c, const uint32_t* a, const uint32_t* b) {
    asm volatile(
        "mma.sync.aligned.m16n8k16.row.col.f32.bf16.bf16.f32 "
        "{%0,%1,%2,%3}, {%4,%5,%6,%7}, {%8,%9}, {%0,%1,%2,%3};\n"
        : "+f"(c[0]), "+f"(c[1]), "+f"(c[2]), "+f"(c[3])
        : "r"(a[0]), "r"(a[1]), "r"(a[2]), "r"(a[3]), "r"(b[0]), "r"(b[1]));
}

#define APAD 136
#define ASTR 12
#define A20  20     // bf16-only A stride: 20 ≡ 20 mod 32 -> conflict-free rows
#define B96  104

// ---------------- one-time split/pack kernels --------------------------------
__global__ void split_rows_h(const float* __restrict__ s, uint32_t* __restrict__ dh,
                             int npairs) {
    int p = blockIdx.x * 256 + threadIdx.x;
    if (p >= npairs) return;
    float2 v = *(const float2*)&s[(size_t)2 * p];
    dh[p] = pack2h(v.x, v.y);
}
__global__ void split_cols_h(const float* __restrict__ s, uint32_t* __restrict__ dh,
                             int N, int npairs) {
    int p = blockIdx.x * 256 + threadIdx.x;
    if (p >= npairs) return;
    int kq = p / N, n = p - kq * N;
    dh[p] = pack2h(s[(size_t)(2 * kq) * N + n], s[(size_t)(2 * kq + 1) * N + n]);
}
__global__ void split_cols_k(const float* __restrict__ s, uint32_t* __restrict__ dh,
                             uint32_t* __restrict__ dl, int N, int npairs) {
    int p = blockIdx.x * 256 + threadIdx.x;
    if (p >= npairs) return;
    int kq = p / N, n = p - kq * N;
    split2(s[(size_t)(2 * kq) * N + n], s[(size_t)(2 * kq + 1) * N + n], dh[p], dl[p]);
}
// V pack (hi only): vp[bh][kq][n], kq in [0,512), n in [0,96)
__global__ void pack_v_h(const float* __restrict__ kv, uint32_t* __restrict__ vh) {
    int p = blockIdx.x * 256 + threadIdx.x;
    if (p >= BHN * 512 * DKK) return;
    int n = p % DKK; int t = p / DKK; int kq = t & 511; int bh = t >> 9;
    int b = bh >> 3, h = bh & 7;
    const float* base = kv + (size_t)(b * SS + 2 * kq) * DDIM + h * DKK + n;
    vh[p] = pack2h(base[0], base[DDIM]);
}

// ============================================================================
// bf16 single-precision GEMM, BK=32 (16 pairs), cp.async 2-stage.
// Block 128x128, 8 warps (2m x 4n), warp tile 64x32. Used for projections.
// ============================================================================
template<bool WF32, bool WPACK>
__global__ __launch_bounds__(256)
void gemm_b1(const uint32_t* __restrict__ Ah, int ldap,
             const uint32_t* __restrict__ Bh, int ldb,
             const float* __restrict__ bias,
             float* __restrict__ C, uint32_t* __restrict__ Ch,
             int ldc, int K)
{
    __shared__ uint32_t sA[2][128][A20];
    __shared__ uint32_t sB[2][16][APAD];

    const int tid = threadIdx.x;
    const int m0 = blockIdx.y * 128, n0 = blockIdx.x * 128;
    const int lane = tid & 31, warp = tid >> 5;
    const int wm = warp >> 2, wn = warp & 3;
    const int r = lane >> 2, kp = lane & 3;

    auto load_stage = [&](int st, int kt) {
        const int kq0 = kt * 16;
        #pragma unroll
        for (int i = 0; i < 2; i++) {
            int c = tid + i * 256;
            int arow = c >> 2, aq = (c & 3) * 4;
            CP16(smem_u32(&sA[st][arow][aq]), Ah + (size_t)(m0 + arow) * ldap + kq0 + aq);
            int brow = c >> 5, bo = (c & 31) * 4;
            CP16(smem_u32(&sB[st][brow][bo]), Bh + (size_t)(kq0 + brow) * ldb + n0 + bo);
        }
        CPCOMMIT();
    };

    float acc[4][4][4];
    #pragma unroll
    for (int i = 0; i < 4; i++)
        #pragma unroll
        for (int j = 0; j < 4; j++)
            #pragma unroll
            for (int e = 0; e < 4; e++) acc[i][j][e] = 0.0f;

    const int KT = K >> 5;
    load_stage(0, 0);
    load_stage(1, 1);

    for (int kt = 0; kt < KT; kt++) {
        const int st = kt & 1;
        CPWAIT1();
        __syncthreads();
        #pragma unroll
        for (int s = 0; s < 2; s++) {
            const int kb = s * 8;
            uint32_t a[4][4], bf[4][2];
            #pragma unroll
            for (int ti = 0; ti < 4; ti++) {
                int row = wm * 64 + ti * 16 + r;
                a[ti][0] = sA[st][row][kb + kp];     a[ti][1] = sA[st][row + 8][kb + kp];
                a[ti][2] = sA[st][row][kb + kp + 4]; a[ti][3] = sA[st][row + 8][kb + kp + 4];
            }
            #pragma unroll
            for (int tj = 0; tj < 4; tj++) {
                int col = wn * 32 + tj * 8 + r;
                bf[tj][0] = sB[st][kb + kp][col]; bf[tj][1] = sB[st][kb + kp + 4][col];
            }
            #pragma unroll
            for (int ti = 0; ti < 4; ti++)
                #pragma unroll
                for (int tj = 0; tj < 4; tj++)
                    mma16816(acc[ti][tj], a[ti], bf[tj]);
        }
        __syncthreads();
        if (kt + 2 < KT) load_stage(st, kt + 2);
        else             CPCOMMIT();
    }

    #pragma unroll
    for (int ti = 0; ti < 4; ti++) {
        int row = m0 + wm * 64 + ti * 16 + r;
        #pragma unroll
        for (int tj = 0; tj < 4; tj++) {
            int gc = n0 + wn * 32 + tj * 8 + 2 * kp;
            float b0 = bias[gc], b1 = bias[gc + 1];
            float v00 = acc[ti][tj][0] + b0, v01 = acc[ti][tj][1] + b1;
            float v10 = acc[ti][tj][2] + b0, v11 = acc[ti][tj][3] + b1;
            if (WF32) {
                *(float2*)&C[(size_t)row * ldc + gc]       = make_float2(v00, v01);
                *(float2*)&C[(size_t)(row + 8) * ldc + gc] = make_float2(v10, v11);
            }
            if (WPACK) {
                int ldcp = ldc >> 1, gp = gc >> 1;
                Ch[(size_t)row * ldcp + gp]       = pack2h(v00, v01);
                Ch[(size_t)(row + 8) * ldcp + gp] = pack2h(v10, v11);
            }
        }
    }
}

// ============================================================================
// Attention scores, bf16 single, BK=32 (3 iters for K=96). Writes bf16-pair w.
// ============================================================================
__global__ __launch_bounds__(256)
void scores_b1(const uint32_t* __restrict__ qh, const uint32_t* __restrict__ kvh,
               const void* __restrict__ pmask, uint32_t* __restrict__ wb)
{
    const int bh = blockIdx.z, b = bh >> 3, h = bh & 7;
    const int m0 = blockIdx.y * 128;
    const int n0 = blockIdx.x * 128;
    if (n0 >= m0 + 128) return;

    __shared__ uint32_t sA[2][128][A20];
    __shared__ uint32_t sB[2][128][A20];

    const uint32_t* Aph = qh  + (size_t)b * SS * DP + h * (DKK / 2);
    const uint32_t* Bph = kvh + (size_t)b * SS * DP + h * (DKK / 2);

    const int tid = threadIdx.x;
    const int lane = tid & 31, warp = tid >> 5;
    const int wm = warp >> 2, wn = warp & 3;
    const int r = lane >> 2, kp = lane & 3;

    auto load_stage = [&](int st, int kt) {
        const int kq0 = kt * 16;
        #pragma unroll
        for (int i = 0; i < 2; i++) {
            int c = tid + i * 256;
            int arow = c >> 2, aq = (c & 3) * 4;
            CP16(smem_u32(&sA[st][arow][aq]), Aph + (size_t)(m0 + arow) * DP + kq0 + aq);
            CP16(smem_u32(&sB[st][arow][aq]), Bph + (size_t)(n0 + arow) * DP + kq0 + aq);
        }
        CPCOMMIT();
    };

    float acc[4][4][4];
    #pragma unroll
    for (int i = 0; i < 4; i++)
        #pragma unroll
        for (int j = 0; j < 4; j++)
            #pragma unroll
            for (int e = 0; e < 4; e++) acc[i][j][e] = 0.0f;

    const int KT = 3;   // 96 / 32
    load_stage(0, 0);
    load_stage(1, 1);

    for (int kt = 0; kt < KT; kt++) {
        const int st = kt & 1;
        CPWAIT1();
        __syncthreads();
        #pragma unroll
        for (int s = 0; s < 2; s++) {
            const int kb = s * 8;
            uint32_t a[4][4], bf[4][2];
            #pragma unroll
            for (int ti = 0; ti < 4; ti++) {
                int row = wm * 64 + ti * 16 + r;
                a[ti][0] = sA[st][row][kb + kp];     a[ti][1] = sA[st][row + 8][kb + kp];
                a[ti][2] = sA[st][row][kb + kp + 4]; a[ti][3] = sA[st][row + 8][kb + kp + 4];
            }
            #pragma unroll
            for (int tj = 0; tj < 4; tj++) {
                int col = wn * 32 + tj * 8 + r;
                bf[tj][0] = sB[st][col][kb + kp]; bf[tj][1] = sB[st][col][kb + kp + 4];
            }
            #pragma unroll
            for (int ti = 0; ti < 4; ti++)
                #pragma unroll
                for (int tj = 0; tj < 4; tj++)
                    mma16816(acc[ti][tj], a[ti], bf[tj]);
        }
        __syncthreads();
        if (kt + 2 < KT) load_stage(st, kt + 2);
        else             CPCOMMIT();
    }

    const float scale = 0.10206207261596575f;   // 1/sqrt(96)
    const unsigned char* m8  = (const unsigned char*)pmask;
    const int*           m32 = (const int*)pmask;
    const int u8 = g_mask_u8;
    uint32_t* wo = wb + (size_t)bh * SS * SP;
    #pragma unroll
    for (int ti = 0; ti < 4; ti++) {
        int qrA = m0 + wm * 64 + ti * 16 + r;
        int qrB = qrA + 8;
        int padA = u8 ? (int)m8[b * SS + qrA] : m32[b * SS + qrA];
        int padB = u8 ? (int)m8[b * SS + qrB] : m32[b * SS + qrB];
        #pragma unroll
        for (int tj = 0; tj < 4; tj++) {
            int gc = n0 + wn * 32 + tj * 8 + 2 * kp;
            float v00 = ((gc     > qrA) || padA) ? MASKV : acc[ti][tj][0] * scale;
            float v01 = ((gc + 1 > qrA) || padA) ? MASKV : acc[ti][tj][1] * scale;
            float v10 = ((gc     > qrB) || padB) ? MASKV : acc[ti][tj][2] * scale;
            float v11 = ((gc + 1 > qrB) || padB) ? MASKV : acc[ti][tj][3] * scale;
            wo[(size_t)qrA * SP + (gc >> 1)] = pack2h(v00, v01);
            wo[(size_t)qrB * SP + (gc >> 1)] = pack2h(v10, v11);
        }
    }
}

// ---------------- column softmax (over q) on bf16 pairs, causal skip ---------
__global__ void col_softmax_b(const uint32_t* __restrict__ wb,
                              float* __restrict__ cm, float* __restrict__ ci)
{
    const int bh = blockIdx.y;
    const int kpair = blockIdx.x * 256 + threadIdx.x;   // 0..511
    const int k0 = kpair * 2;
    const int qs = k0 & ~127;
    const uint32_t* wc = wb + (size_t)bh * SS * SP + kpair;
    float m0v = -1e30f, s0 = 0.0f, m1v = -1e30f, s1 = 0.0f;
    for (int q = qs; q < SS; q++) {
        float2 v = unpack2(wc[(size_t)q * SP]);
        if (v.x > m0v) { s0 = s0 * __expf(m0v - v.x) + 1.0f; m0v = v.x; }
        else           { s0 += __expf(v.x - m0v); }
        if (v.y > m1v) { s1 = s1 * __expf(m1v - v.y) + 1.0f; m1v = v.y; }
        else           { s1 += __expf(v.y - m1v); }
    }
    s0 += (float)qs * __expf(MASKV - m0v);
    s1 += (float)qs * __expf(MASKV - m1v);
    cm[bh * SS + k0]     = m0v;  ci[bh * SS + k0]     = 1.0f / s0;
    cm[bh * SS + k0 + 1] = m1v;  ci[bh * SS + k0 + 1] = 1.0f / s1;
}

// ============================================================================
// o = softmax(w) @ v, bf16 single, BK=32 (32 iters). A = exp(w-cm)*ci built
// in-kernel from bf16 pairs; B = V hi via cp.async 2-stage. Above-diagonal
// k-tiles use the constant MASKV (w never stored there).
// ============================================================================
__global__ __launch_bounds__(256)
void pv_b1(const uint32_t* __restrict__ wb, const uint32_t* __restrict__ vh,
           const float* __restrict__ cm, const float* __restrict__ ci,
           float* __restrict__ o)
{
    __shared__ uint32_t sA[128][A20];
    __shared__ uint32_t sB[2][16][B96];

    const int bh = blockIdx.y, b = bh >> 3, h = bh & 7;
    const int m0 = blockIdx.x * 128;
    const uint32_t* Wp = wb + (size_t)bh * SS * SP;
    const uint32_t* V  = vh + (size_t)bh * 512 * DKK;
    const float* cmp = cm + bh * SS;
    const float* cip = ci + bh * SS;
    const int tid = threadIdx.x;
    const int lane = tid & 31, warp = tid >> 5;
    const int wm = warp >> 2, wn = warp & 3;
    const int r = lane >> 2, kp = lane & 3;

    auto load_B = [&](int st, int kt) {
        if (tid < 192) {
            #pragma unroll
            for (int i = 0; i < 2; i++) {
                int ch = tid * 2 + i;
                int row = ch / 24, off = (ch % 24) * 4;
                CP16(smem_u32(&sB[st][row][off]), V + (size_t)(kt * 16 + row) * DKK + off);
            }
        }
        CPCOMMIT();
    };

    const int arow = tid >> 1, acp = (tid & 1) * 8;   // A build: row, 8 pair-cols
    uint4 aP0, aP1;
    auto prefetchA = [&](int kt) {
        const uint32_t* src = Wp + (size_t)(m0 + arow) * SP + kt * 16 + acp;
        aP0 = *(const uint4*)src;
        aP1 = *(const uint4*)(src + 4);
    };

    float acc[4][3][4];
    #pragma unroll
    for (int i = 0; i < 4; i++)
        #pragma unroll
        for (int j = 0; j < 3; j++)
            #pragma unroll
            for (int e = 0; e < 4; e++) acc[i][j][e] = 0.0f;

    const int KT = 32;
    prefetchA(0);
    load_B(0, 0);
    load_B(1, 1);

    for (int kt = 0; kt < KT; kt++) {
        const int st = kt & 1;
        const bool above = kt * 32 >= m0 + 128;
        uint32_t aw[8];
        *(uint4*)aw = aP0; *(uint4*)(aw + 4) = aP1;
        #pragma unroll
        for (int j = 0; j < 8; j++) {
            int kk = (kt * 16 + acp + j) * 2;
            float2 v = above ? make_float2(MASKV, MASKV) : unpack2(aw[j]);
            float px = __expf(v.x - cmp[kk])     * cip[kk];
            float py = __expf(v.y - cmp[kk + 1]) * cip[kk + 1];
            sA[arow][acp + j] = pack2h(px, py);
        }
        CPWAIT1();
        __syncthreads();
        if (kt + 1 < KT && (kt + 1) * 32 < m0 + 128) prefetchA(kt + 1);
        #pragma unroll
        for (int s = 0; s < 2; s++) {
            const int kb = s * 8;
            uint32_t a[4][4], bf[3][2];
            #pragma unroll
            for (int ti = 0; ti < 4; ti++) {
                int row = wm * 64 + ti * 16 + r;
                a[ti][0] = sA[row][kb + kp];     a[ti][1] = sA[row + 8][kb + kp];
                a[ti][2] = sA[row][kb + kp + 4]; a[ti][3] = sA[row + 8][kb + kp + 4];
            }
            #pragma unroll
            for (int tj = 0; tj < 3; tj++) {
                int col = wn * 24 + tj * 8 + r;
                bf[tj][0] = sB[st][kb + kp][col]; bf[tj][1] = sB[st][kb + kp + 4][col];
            }
            #pragma unroll
            for (int ti = 0; ti < 4; ti++)
                #pragma unroll
                for (int tj = 0; tj < 3; tj++)
                    mma16816(acc[ti][tj], a[ti], bf[tj]);
        }
        __syncthreads();
        if (kt + 2 < KT) load_B(st, kt + 2);
        else             CPCOMMIT();
    }

    #pragma unroll
    for (int ti = 0; ti < 4; ti++) {
        int row = m0 + wm * 64 + ti * 16 + r;
        float* oA = o + (size_t)(b * SS + row) * DDIM + h * DKK;
        float* oB = o + (size_t)(b * SS + row + 8) * DDIM + h * DKK;
        #pragma unroll
        for (int tj = 0; tj < 3; tj++) {
            int gc = wn * 24 + tj * 8 + 2 * kp;
            *(float2*)&oA[gc] = make_float2(acc[ti][tj][0], acc[ti][tj][1]);
            *(float2*)&oB[gc] = make_float2(acc[ti][tj][2], acc[ti][tj][3]);
        }
    }
}

// ============================================================================
// bf16x3 GEMM (FFN path only) — unchanged from the passing R15 kernel.
// ============================================================================
template<bool RELU, bool WF32, bool WPACK>
__global__ __launch_bounds__(256)
void gemm_tc(const uint32_t* __restrict__ Ah, const uint32_t* __restrict__ Al, int ldap,
             const uint32_t* __restrict__ Bh, const uint32_t* __restrict__ Bl, int ldb,
             const float* __restrict__ bias,
             float* __restrict__ C, uint32_t* __restrict__ Ch, uint32_t* __restrict__ Cl,
             int ldc, int K)
{
    __shared__ uint32_t sAh[2][128][ASTR], sAl[2][128][ASTR];
    __shared__ uint32_t sBh[2][8][APAD],  sBl[2][8][APAD];

    const int tid = threadIdx.x;
    const int m0 = blockIdx.y * 128, n0 = blockIdx.x * 128;
    const int lane = tid & 31, warp = tid >> 5;
    const int wm = warp >> 2, wn = warp & 3;
    const int r = lane >> 2, kp = lane & 3;

    const int arow = tid >> 1, aq = (tid & 1) * 4;
    const int bkb = tid >> 5,  bn4 = lane * 4;
    const size_t aoff = (size_t)(m0 + arow) * ldap + aq;
    const size_t boff = (size_t)bkb * ldb + n0 + bn4;

    auto load_stage = [&](int st, int kt) {
        const int kq0 = kt * 8;
        CP16(smem_u32(&sAh[st][arow][aq]), Ah + aoff + kq0);
        CP16(smem_u32(&sAl[st][arow][aq]), Al + aoff + kq0);
        CP16(smem_u32(&sBh[st][bkb][bn4]), Bh + boff + (size_t)kq0 * ldb);
        CP16(smem_u32(&sBl[st][bkb][bn4]), Bl + boff + (size_t)kq0 * ldb);
        CPCOMMIT();
    };

    float c[4][4][4];
    #pragma unroll
    for (int i = 0; i < 4; i++)
        #pragma unroll
        for (int j = 0; j < 4; j++)
            #pragma unroll
            for (int e = 0; e < 4; e++) c[i][j][e] = 0.0f;

    const int KT = K >> 4;
    load_stage(0, 0);
    load_stage(1, 1);

    for (int kt = 0; kt < KT; kt++) {
        const int st = kt & 1;
        CPWAIT1();
        __syncthreads();

        uint32_t ah[4][4], al[4][4], bh[4][2], bl[4][2];
        #pragma unroll
        for (int ti = 0; ti < 4; ti++) {
            int row = wm * 64 + ti * 16 + r;
            ah[ti][0] = sAh[st][row][kp];     ah[ti][1] = sAh[st][row + 8][kp];
            ah[ti][2] = sAh[st][row][kp + 4]; ah[ti][3] = sAh[st][row + 8][kp + 4];
            al[ti][0] = sAl[st][row][kp];     al[ti][1] = sAl[st][row + 8][kp];
            al[ti][2] = sAl[st][row][kp + 4]; al[ti][3] = sAl[st][row + 8][kp + 4];
        }
        #pragma unroll
        for (int tj = 0; tj < 4; tj++) {
            int col = wn * 32 + tj * 8 + r;
            bh[tj][0] = sBh[st][kp][col]; bh[tj][1] = sBh[st][kp + 4][col];
            bl[tj][0] = sBl[st][kp][col]; bl[tj][1] = sBl[st][kp + 4][col];
        }
        #pragma unroll
        for (int ti = 0; ti < 4; ti++)
            #pragma unroll
            for (int tj = 0; tj < 4; tj++) {
                mma16816(c[ti][tj], ah[ti], bh[tj]);
                mma16816(c[ti][tj], ah[ti], bl[tj]);
                mma16816(c[ti][tj], al[ti], bh[tj]);
            }
        __syncthreads();
        if (kt + 2 < KT) load_stage(st, kt + 2);
        else             CPCOMMIT();
    }

    #pragma unroll
    for (int ti = 0; ti < 4; ti++) {
        int row = m0 + wm * 64 + ti * 16 + r;
        #pragma unroll
        for (int tj = 0; tj < 4; tj++) {
            int gc = n0 + wn * 32 + tj * 8 + 2 * kp;
            float b0 = bias[gc], b1 = bias[gc + 1];
            float v00 = c[ti][tj][0] + b0, v01 = c[ti][tj][1] + b1;
            float v10 = c[ti][tj][2] + b0, v11 = c[ti][tj][3] + b1;
            if (RELU) {
                v00 = fmaxf(v00, 0.f); v01 = fmaxf(v01, 0.f);
                v10 = fmaxf(v10, 0.f); v11 = fmaxf(v11, 0.f);
            }
            if (WF32) {
                *(float2*)&C[(size_t)row * ldc + gc]       = make_float2(v00, v01);
                *(float2*)&C[(size_t)(row + 8) * ldc + gc] = make_float2(v10, v11);
            }
            if (WPACK) {
                int ldcp = ldc >> 1, gp = gc >> 1;
                uint32_t ph, pl;
                split2(v00, v01, ph, pl);
                Ch[(size_t)row * ldcp + gp] = ph; Cl[(size_t)row * ldcp + gp] = pl;
                split2(v10, v11, ph, pl);
                Ch[(size_t)(row + 8) * ldcp + gp] = ph; Cl[(size_t)(row + 8) * ldcp + gp] = pl;
            }
        }
    }
}

// ---------------- fused residual + LayerNorm (optionally writes packed) ------
template<bool PACK>
__global__ void add_ln_k(const float* __restrict__ o, const float* __restrict__ x,
                         const float* __restrict__ g, const float* __restrict__ bta,
                         float* __restrict__ out,
                         uint32_t* __restrict__ oh, uint32_t* __restrict__ ol)
{
    __shared__ float red[256];
    const int row = blockIdx.x;
    const int tid = threadIdx.x;
    const float* op = o + (size_t)row * DDIM;
    const float* xp = x + (size_t)row * DDIM;
    const bool has2 = tid < 128;
    float2 v0, v1 = make_float2(0.f, 0.f);
    {
        float2 a = *(const float2*)&op[2 * tid];
        float2 b = *(const float2*)&xp[2 * tid];
        v0 = make_float2(a.x + b.x, a.y + b.y);
    }
    if (has2) {
        float2 a = *(const float2*)&op[512 + 2 * tid];
        float2 b = *(const float2*)&xp[512 + 2 * tid];
        v1 = make_float2(a.x + b.x, a.y + b.y);
    }
    float lsum = v0.x + v0.y + v1.x + v1.y;
    red[tid] = lsum; __syncthreads();
    for (int st = 128; st > 0; st >>= 1) {
        if (tid < st) red[tid] += red[tid + st];
        __syncthreads();
    }
    float mean = red[0] * (1.0f / 768.0f);
    __syncthreads();
    float d0 = v0.x - mean, d1 = v0.y - mean;
    float lsq = d0 * d0 + d1 * d1;
    if (has2) { float d2 = v1.x - mean, d3 = v1.y - mean; lsq += d2 * d2 + d3 * d3; }
    red[tid] = lsq; __syncthreads();
    for (int st = 128; st > 0; st >>= 1) {
        if (tid < st) red[tid] += red[tid + st];
        __syncthreads();
    }
    float inv = rsqrtf(red[0] * (1.0f / 768.0f) + 1e-5f);

    {
        int c0 = 2 * tid;
        float y0 = (v0.x - mean) * inv * g[c0] + bta[c0];
        float y1 = (v0.y - mean) * inv * g[c0 + 1] + bta[c0 + 1];
        *(float2*)&out[(size_t)row * DDIM + c0] = make_float2(y0, y1);
        if (PACK) {
            uint32_t ph, pl; split2(y0, y1, ph, pl);
            oh[(size_t)row * DP + tid] = ph; ol[(size_t)row * DP + tid] = pl;
        }
    }
    if (has2) {
        int c0 = 512 + 2 * tid;
        float y0 = (v1.x - mean) * inv * g[c0] + bta[c0];
        float y1 = (v1.y - mean) * inv * g[c0 + 1] + bta[c0 + 1];
        *(float2*)&out[(size_t)row * DDIM + c0] = make_float2(y0, y1);
        if (PACK) {
            uint32_t ph, pl; split2(y0, y1, ph, pl);
            oh[(size_t)row * DP + 256 + tid] = ph; ol[(size_t)row * DP + 256 + tid] = pl;
        }
    }
}

// ---------------- launch -----------------------------------------------------
extern "C" void kernel_launch(void* const* d_in, const int* in_sizes, int n_in,
                              void* d_out, int out_size)
{
    const float* x     = (const float*)d_in[0];
    const void*  amask = d_in[1];
    const float* a1_Wq = (const float*)d_in[2],  *a1_bq = (const float*)d_in[3];
    const float* a1_Wv = (const float*)d_in[4],  *a1_bv = (const float*)d_in[5];
    const float* a1_g  = (const float*)d_in[6],  *a1_b  = (const float*)d_in[7];
    const float* a2_Wq = (const float*)d_in[8],  *a2_bq = (const float*)d_in[9];
    const float* a2_Wv = (const float*)d_in[10], *a2_bv = (const float*)d_in[11];
    const float* a2_g  = (const float*)d_in[12], *a2_b  = (const float*)d_in[13];
    const float* f_W1  = (const float*)d_in[14], *f_b1  = (const float*)d_in[15];
    const float* f_W2  = (const float*)d_in[16], *f_b2  = (const float*)d_in[17];
    const float* f_g   = (const float*)d_in[18], *f_b   = (const float*)d_in[19];
    float* out = (float*)d_out;

    float *p_cm, *p_ci, *p_kv, *p_t0, *p_x1, *p_x2;
    uint32_t *p_wb;
    cudaGetSymbolAddress((void**)&p_wb, g_wb);
    cudaGetSymbolAddress((void**)&p_cm, g_cm);
    cudaGetSymbolAddress((void**)&p_ci, g_ci);
    cudaGetSymbolAddress((void**)&p_kv, g_kv);
    cudaGetSymbolAddress((void**)&p_t0, g_t0);
    cudaGetSymbolAddress((void**)&p_x1, g_x1);
    cudaGetSymbolAddress((void**)&p_x2, g_x2);

    uint32_t *xh,*qh,*kvh,*x1h,*x1l,*x2h,*x2l,*hh,*hl,*vh;
    uint32_t *w1qh,*w1vh,*w2qh,*w2vh,*wf1h,*wf1l,*wf2h,*wf2l;
    cudaGetSymbolAddress((void**)&xh,  g_xh);
    cudaGetSymbolAddress((void**)&qh,  g_qh);
    cudaGetSymbolAddress((void**)&kvh, g_kvh);
    cudaGetSymbolAddress((void**)&x1h, g_x1h); cudaGetSymbolAddress((void**)&x1l, g_x1l);
    cudaGetSymbolAddress((void**)&x2h, g_x2h); cudaGetSymbolAddress((void**)&x2l, g_x2l);
    cudaGetSymbolAddress((void**)&hh,  g_hh);  cudaGetSymbolAddress((void**)&hl,  g_hl);
    cudaGetSymbolAddress((void**)&vh,  g_vh);
    cudaGetSymbolAddress((void**)&w1qh, g_w1qh);
    cudaGetSymbolAddress((void**)&w1vh, g_w1vh);
    cudaGetSymbolAddress((void**)&w2qh, g_w2qh);
    cudaGetSymbolAddress((void**)&w2vh, g_w2vh);
    cudaGetSymbolAddress((void**)&wf1h, g_wf1h); cudaGetSymbolAddress((void**)&wf1l, g_wf1l);
    cudaGetSymbolAddress((void**)&wf2h, g_wf2h); cudaGetSymbolAddress((void**)&wf2l, g_wf2l);

    probe_mask_k<<<1, 256>>>((const unsigned char*)amask);

    split_rows_h<<<(MROWS * DP + 255) / 256, 256>>>(x, xh, MROWS * DP);
    split_cols_h<<<(DP * DDIM + 255) / 256, 256>>>(a1_Wq, w1qh, DDIM, DP * DDIM);
    split_cols_h<<<(DP * DDIM + 255) / 256, 256>>>(a1_Wv, w1vh, DDIM, DP * DDIM);
    split_cols_h<<<(DP * DDIM + 255) / 256, 256>>>(a2_Wq, w2qh, DDIM, DP * DDIM);
    split_cols_h<<<(DP * DDIM + 255) / 256, 256>>>(a2_Wv, w2vh, DDIM, DP * DDIM);
    split_cols_k<<<(DP * FFD  + 255) / 256, 256>>>(f_W1, wf1h, wf1l, FFD,  DP * FFD);
    split_cols_k<<<(FP * DDIM + 255) / 256, 256>>>(f_W2, wf2h, wf2l, DDIM, FP * DDIM);

    const dim3 gProj(6, 64);
    const dim3 gScore(8, 8, 64);
    const dim3 gSoft(2, 64);
    const dim3 gAO(8, 64);
    const dim3 gF1(8, 64);
    const int  gPackV = (BHN * 512 * DKK + 255) / 256;

    // ---- MHA layer 1 ----
    gemm_b1<false, true><<<gProj, 256>>>(xh, DP, w1qh, DDIM, a1_bq,
                                         (float*)nullptr, qh, DDIM, DDIM);
    gemm_b1<true,  true><<<gProj, 256>>>(xh, DP, w1vh, DDIM, a1_bv,
                                         p_kv, kvh, DDIM, DDIM);
    pack_v_h<<<gPackV, 256>>>(p_kv, vh);
    scores_b1<<<gScore, 256>>>(qh, kvh, amask, p_wb);
    col_softmax_b<<<gSoft, 256>>>(p_wb, p_cm, p_ci);
    pv_b1<<<gAO, 256>>>(p_wb, vh, p_cm, p_ci, p_t0);
    add_ln_k<true><<<MROWS, 256>>>(p_t0, x, a1_g, a1_b, p_x1, x1h, x1l);

    // ---- MHA layer 2 ----
    gemm_b1<false, true><<<gProj, 256>>>(x1h, DP, w2qh, DDIM, a2_bq,
                                         (float*)nullptr, qh, DDIM, DDIM);
    gemm_b1<true,  true><<<gProj, 256>>>(x1h, DP, w2vh, DDIM, a2_bv,
                                         p_kv, kvh, DDIM, DDIM);
    pack_v_h<<<gPackV, 256>>>(p_kv, vh);
    scores_b1<<<gScore, 256>>>(qh, kvh, amask, p_wb);
    col_softmax_b<<<gSoft, 256>>>(p_wb, p_cm, p_ci);
    pv_b1<<<gAO, 256>>>(p_wb, vh, p_cm, p_ci, p_t0);
    add_ln_k<true><<<MROWS, 256>>>(p_t0, p_x1, a2_g, a2_b, p_x2, x2h, x2l);

    // ---- FFN (bf16x3 for precision) ----
    gemm_tc<true,  false, true><<<gF1,   256>>>(x2h, x2l, DP, wf1h, wf1l, FFD, f_b1,
                                                (float*)nullptr, hh, hl, FFD, DDIM);
    gemm_tc<false, true, false><<<gProj, 256>>>(hh, hl, FP, wf2h, wf2l, DDIM, f_b2,
                                                p_t0, (uint32_t*)nullptr, (uint32_t*)nullptr,
                                                DDIM, FFD);
    add_ln_k<false><<<MROWS, 256>>>(p_t0, p_x2, f_g, f_b, out,
                                    (uint32_t*)nullptr, (uint32_t*)nullptr);
}